// round 15
// baseline (speedup 1.0000x reference)
#include <cuda_runtime.h>
#include <cuda_bf16.h>
#include <math.h>

// Problem constants
#define BB 2
#define SS 2048
#define DD 1024
#define HH 16
#define HD 64
#define CC 1024
#define MM (BB*SS)          // 4096 rows
#define D3 (3*DD)           // 3072
#define D4 (4*DD)           // 4096
#define D6 (6*DD)           // 6144

typedef unsigned long long u64;
typedef unsigned int u32;

__device__ __forceinline__ u32 to_tf32(float f) {
    u32 r; asm("cvt.rna.tf32.f32 %0,%1;" : "=r"(r) : "f"(f)); return r;
}
__device__ __forceinline__ float to_tf32f(float f) {
    return __uint_as_float(to_tf32(f));
}
__device__ __forceinline__ u32 smem_u32(const void* p) {
    u32 a;
    asm("{ .reg .u64 t; cvta.to.shared.u64 t, %1; cvt.u32.u64 %0, t; }"
        : "=r"(a) : "l"(p));
    return a;
}
__device__ __forceinline__ void cp16(u32 dst, const float* src) {
    asm volatile("cp.async.cg.shared.global [%0], [%1], 16;"
                 :: "r"(dst), "l"(src));
}
#define CP_COMMIT() asm volatile("cp.async.commit_group;" ::: "memory")
#define CP_WAIT(N)  asm volatile("cp.async.wait_group %0;" :: "n"(N) : "memory")

// Scratch (device globals; no allocation allowed)
__device__ float g_mods[BB*D6];
__device__ float g_h[MM*DD];       // LN1 out, later LN2 out
__device__ float g_qkv[MM*D3];
__device__ float g_o[MM*DD];
__device__ float g_xmid[MM*DD];
__device__ float g_mlp[MM*D4];
// tf32-pre-rounded weights
__device__ float g_wq[D3*DD];
__device__ float g_wo[DD*DD];
__device__ float g_w1[D4*DD];
__device__ float g_w2[DD*D4];

// ---------------------------------------------------------------------------
// 0) weight convert: dst = tf32_rna(src)
// ---------------------------------------------------------------------------
__global__ void k_wcvt(const float* __restrict__ src, float* __restrict__ dst, int n)
{
    int i = (blockIdx.x * blockDim.x + threadIdx.x) * 4;
    if (i >= n) return;
    float4 v = *(const float4*)(src + i);
    *(uint4*)(dst + i) = make_uint4(to_tf32(v.x), to_tf32(v.y),
                                    to_tf32(v.z), to_tf32(v.w));
}

// ---------------------------------------------------------------------------
// 1) mods = c @ ada_w.T + ada_b
// ---------------------------------------------------------------------------
__global__ void k_mods(const float* __restrict__ c,
                       const float* __restrict__ ada_w,
                       const float* __restrict__ ada_b)
{
    int gw = (blockIdx.x * blockDim.x + threadIdx.x) >> 5;
    int lane = threadIdx.x & 31;
    if (gw >= BB * D6) return;
    int b = gw / D6, j = gw - b * D6;
    const float* cv = c + (size_t)b * CC;
    const float* wv = ada_w + (size_t)j * CC;
    float s = 0.f;
    #pragma unroll 4
    for (int k = lane; k < CC; k += 32) s += cv[k] * wv[k];
    #pragma unroll
    for (int o = 16; o > 0; o >>= 1) s += __shfl_xor_sync(0xffffffffu, s, o);
    if (lane == 0) g_mods[gw] = s + ada_b[j];
}

// ---------------------------------------------------------------------------
// 2) LayerNorm + adaLN modulate (output pre-rounded to tf32: feeds GEMM only)
// ---------------------------------------------------------------------------
__global__ void __launch_bounds__(256) k_ln_mod(const float* __restrict__ x,
                                                const float* __restrict__ w,
                                                int scale_off, int shift_off,
                                                float* __restrict__ out)
{
    int row = blockIdx.x;
    int b = row >> 11;
    const float4* xr = (const float4*)(x + (size_t)row * DD);
    int t = threadIdx.x;
    float4 xv = xr[t];
    float s  = xv.x + xv.y + xv.z + xv.w;
    float ss = xv.x*xv.x + xv.y*xv.y + xv.z*xv.z + xv.w*xv.w;
    #pragma unroll
    for (int o = 16; o > 0; o >>= 1) {
        s  += __shfl_xor_sync(0xffffffffu, s, o);
        ss += __shfl_xor_sync(0xffffffffu, ss, o);
    }
    __shared__ float sm[8], sm2[8];
    int wid = t >> 5, lane = t & 31;
    if (lane == 0) { sm[wid] = s; sm2[wid] = ss; }
    __syncthreads();
    if (t == 0) {
        float a = 0.f, a2 = 0.f;
        #pragma unroll
        for (int i = 0; i < 8; i++) { a += sm[i]; a2 += sm2[i]; }
        sm[0] = a; sm2[0] = a2;
    }
    __syncthreads();
    float mu  = sm[0]  * (1.f / DD);
    float var = sm2[0] * (1.f / DD) - mu * mu;
    float rstd = rsqrtf(var + 1e-5f);
    const float* md = g_mods + (size_t)b * D6;
    int j = t * 4;
    float4 wv = *(const float4*)(w + j);
    float4 sc = *(const float4*)(md + scale_off + j);
    float4 sh = *(const float4*)(md + shift_off + j);
    float4 ov;
    ov.x = to_tf32f((xv.x - mu) * rstd * wv.x * (1.f + sc.x) + sh.x);
    ov.y = to_tf32f((xv.y - mu) * rstd * wv.y * (1.f + sc.y) + sh.y);
    ov.z = to_tf32f((xv.z - mu) * rstd * wv.z * (1.f + sc.z) + sh.z);
    ov.w = to_tf32f((xv.w - mu) * rstd * wv.w * (1.f + sc.w) + sh.w);
    ((float4*)(out + (size_t)row * DD))[t] = ov;
}

// ---------------------------------------------------------------------------
// 3) tf32 tensor-core GEMM: C[M,N] = A[M,K] @ Bw[N,K]^T (+ epilogue)
//    Inputs are PRE-ROUNDED to tf32 by producers -> cp.async stages raw bits.
//    128x128x32 tile, 256 threads (8 warps, 2x4), warp = 64x32 via
//    4x4 m16n8k8 mma tiles. SMEM stride 36 floats -> conflict-free frag LDS.
//    2-stage cp.async ring (73.7KB dyn, 2 CTAs/SM), copies overlap compute.
//    EPI: 0=store, 1=gate*acc+add, 2=gelu(acc+bias)->tf32, 3=gate*(acc+bias)+add
// ---------------------------------------------------------------------------
#define SMS 36                    // smem row stride (floats)
#define STG_MAT (128 * SMS)       // one matrix per stage (floats)
#define STG_SZ  (2 * STG_MAT)     // A+B per stage
#define GSMEM   (2 * STG_SZ * 4)  // 73728 bytes

template<int EPI>
__global__ void __launch_bounds__(256) k_gemm(const float* __restrict__ A,
                                              const float* __restrict__ Bw,
                                              const float* __restrict__ bias,
                                              const float* __restrict__ add,
                                              float* __restrict__ C,
                                              int M, int N, int K, int gate_off)
{
    extern __shared__ float smr[];   // 2 stages: [A 128*36 | B 128*36]

    const int tid = threadIdx.x;
    const int wid = tid >> 5, lane = tid & 31;
    const int warp_m = wid & 1;
    const int warp_n = wid >> 1;
    const int gid = lane >> 2, tig = lane & 3;
    const int bm = blockIdx.y * 128, bn = blockIdx.x * 128;

    const int arow = tid >> 1;
    const int ak = (tid & 1) * 16;
    const float* Ap = A  + (size_t)(bm + arow) * K + ak;
    const float* Bp = Bw + (size_t)(bn + arow) * K + ak;

    const u32 sbase = smem_u32(smr);
    const u32 adst = sbase + (u32)(arow * SMS + ak) * 4;
    const u32 bofs = (u32)STG_MAT * 4;

    float acc[4][4][4];
    #pragma unroll
    for (int mt = 0; mt < 4; mt++)
        #pragma unroll
        for (int nt = 0; nt < 4; nt++)
            #pragma unroll
            for (int r = 0; r < 4; r++) acc[mt][nt][r] = 0.f;

    const int nch = K / 32;

    // prologue: async-copy chunk 0 into stage 0
    #pragma unroll
    for (int j = 0; j < 4; j++) {
        cp16(adst + j * 16, Ap + j * 4);
        cp16(adst + bofs + j * 16, Bp + j * 4);
    }
    CP_COMMIT();

    for (int ch = 0; ch < nch; ch++) {
        if (ch + 1 < nch) {
            u32 soff = (u32)(((ch + 1) & 1) * STG_SZ) * 4;
            const float* ap = Ap + (ch + 1) * 32;
            const float* bp = Bp + (ch + 1) * 32;
            #pragma unroll
            for (int j = 0; j < 4; j++) {
                cp16(adst + soff + j * 16, ap + j * 4);
                cp16(adst + soff + bofs + j * 16, bp + j * 4);
            }
            CP_COMMIT();
            CP_WAIT(1);          // chunk ch arrived
        } else {
            CP_WAIT(0);
        }
        __syncthreads();

        const float* As = smr + (ch & 1) * STG_SZ;
        const float* Bs = As + STG_MAT;

        #pragma unroll
        for (int ks = 0; ks < 4; ks++) {
            const int kb = ks * 8;
            u32 afr[4][4];
            #pragma unroll
            for (int mt = 0; mt < 4; mt++) {
                int m0 = warp_m * 64 + mt * 16;
                afr[mt][0] = __float_as_uint(As[(m0 + gid)     * SMS + kb + tig]);
                afr[mt][1] = __float_as_uint(As[(m0 + gid + 8) * SMS + kb + tig]);
                afr[mt][2] = __float_as_uint(As[(m0 + gid)     * SMS + kb + tig + 4]);
                afr[mt][3] = __float_as_uint(As[(m0 + gid + 8) * SMS + kb + tig + 4]);
            }
            u32 bfr[4][2];
            #pragma unroll
            for (int nt = 0; nt < 4; nt++) {
                int n0 = warp_n * 32 + nt * 8;
                bfr[nt][0] = __float_as_uint(Bs[(n0 + gid) * SMS + kb + tig]);
                bfr[nt][1] = __float_as_uint(Bs[(n0 + gid) * SMS + kb + tig + 4]);
            }
            #pragma unroll
            for (int mt = 0; mt < 4; mt++)
                #pragma unroll
                for (int nt = 0; nt < 4; nt++) {
                    asm volatile(
                        "mma.sync.aligned.m16n8k8.row.col.f32.tf32.tf32.f32 "
                        "{%0,%1,%2,%3},{%4,%5,%6,%7},{%8,%9},{%0,%1,%2,%3};"
                        : "+f"(acc[mt][nt][0]), "+f"(acc[mt][nt][1]),
                          "+f"(acc[mt][nt][2]), "+f"(acc[mt][nt][3])
                        : "r"(afr[mt][0]), "r"(afr[mt][1]),
                          "r"(afr[mt][2]), "r"(afr[mt][3]),
                          "r"(bfr[nt][0]), "r"(bfr[nt][1]));
                }
        }
        __syncthreads();   // WAR: readers done before next cp.async overwrites
    }

    #pragma unroll
    for (int mt = 0; mt < 4; mt++) {
        #pragma unroll
        for (int half = 0; half < 2; half++) {
            int m = bm + warp_m * 64 + mt * 16 + gid + half * 8;
            int bb = m >> 11;
            #pragma unroll
            for (int nt = 0; nt < 4; nt++) {
                int n = bn + warp_n * 32 + nt * 8 + tig * 2;
                float v0 = acc[mt][nt][half * 2];
                float v1 = acc[mt][nt][half * 2 + 1];
                if (EPI == 0) {
                } else if (EPI == 1) {
                    v0 = g_mods[(size_t)bb * D6 + gate_off + n]     * v0
                         + add[(size_t)m * N + n];
                    v1 = g_mods[(size_t)bb * D6 + gate_off + n + 1] * v1
                         + add[(size_t)m * N + n + 1];
                } else if (EPI == 2) {
                    float t0 = v0 + bias[n],     t1 = v1 + bias[n + 1];
                    v0 = to_tf32f(0.5f * t0 * (1.f + erff(t0 * 0.70710678118654752f)));
                    v1 = to_tf32f(0.5f * t1 * (1.f + erff(t1 * 0.70710678118654752f)));
                } else {
                    float t0 = v0 + bias[n],     t1 = v1 + bias[n + 1];
                    v0 = g_mods[(size_t)bb * D6 + gate_off + n]     * t0
                         + add[(size_t)m * DD + n];
                    v1 = g_mods[(size_t)bb * D6 + gate_off + n + 1] * t1
                         + add[(size_t)m * DD + n + 1];
                }
                *(float2*)&C[(size_t)m * N + n] = make_float2(v0, v1);
            }
        }
    }
}

// ---------------------------------------------------------------------------
// 4) RoPE in place on all of q,k,v (reference applies it to v too)
// ---------------------------------------------------------------------------
__global__ void k_rope(const float* __restrict__ cosT, const float* __restrict__ sinT)
{
    int t = blockIdx.x * blockDim.x + threadIdx.x;
    if (t >= BB * SS * 3 * HH * 32) return;
    int d  = t & 31;  int u = t >> 5;
    int h  = u & 15;  u >>= 4;
    int m3 = u % 3;   u /= 3;
    int s  = u & 2047;
    int b  = u >> 11;
    size_t base = ((((size_t)(b * SS + s)) * 3 + m3) * HH + h) * HD;
    float c  = cosT[s * HD + d];
    float sn = sinT[s * HD + d];
    float v1 = g_qkv[base + d];
    float v2 = g_qkv[base + d + 32];
    g_qkv[base + d]      = v1 * c - v2 * sn;
    g_qkv[base + d + 32] = v2 * c + v1 * sn;
}

// ---------------------------------------------------------------------------
// 5) Flash attention on tf32 tensor cores (R6-proven; g_o store pre-rounded).
// ---------------------------------------------------------------------------
#define KST 68
#define VST 72
#define ATT_SMEM ((64*KST + 64*VST + 64*KST) * 4)

__global__ void __launch_bounds__(128) k_attn()
{
    extern __shared__ u32 dyn[];
    u32* Ks = dyn;
    u32* Vs = dyn + 64 * KST;
    u32* Ps = dyn + 64 * KST + 64 * VST;

    int qt = blockIdx.x, h = blockIdx.y, b = blockIdx.z;
    int tid = threadIdx.x;
    int wid = tid >> 5, lane = tid & 31;
    int gid = lane >> 2, tig = lane & 3;
    int m0w = wid * 16;

    size_t qbase = (((size_t)(b * SS + qt * 64)) * 3 + 0) * DD + h * HD;
    {
        int r = tid >> 1, c0 = (tid & 1) * 32;
        const float* src = g_qkv + qbase + (size_t)r * D3 + c0;
        u32* dst = Ps + r * KST + c0;
        #pragma unroll
        for (int j = 0; j < 8; j++) {
            float4 v = *(const float4*)(src + j * 4);
            dst[j*4+0] = to_tf32(v.x); dst[j*4+1] = to_tf32(v.y);
            dst[j*4+2] = to_tf32(v.z); dst[j*4+3] = to_tf32(v.w);
        }
    }
    __syncthreads();

    u32 qa[8][4];
    #pragma unroll
    for (int ks = 0; ks < 8; ks++) {
        int kb = ks * 8;
        qa[ks][0] = Ps[(m0w + gid)     * KST + kb + tig];
        qa[ks][1] = Ps[(m0w + gid + 8) * KST + kb + tig];
        qa[ks][2] = Ps[(m0w + gid)     * KST + kb + tig + 4];
        qa[ks][3] = Ps[(m0w + gid + 8) * KST + kb + tig + 4];
    }

    float mx0 = -1e30f, mx1 = -1e30f, l0 = 0.f, l1 = 0.f;
    float oa[8][4];
    #pragma unroll
    for (int nt = 0; nt < 8; nt++)
        #pragma unroll
        for (int r = 0; r < 4; r++) oa[nt][r] = 0.f;

    for (int kt = 0; kt < SS / 64; kt++) {
        __syncthreads();
        {
            int r = tid >> 1, c0 = (tid & 1) * 32;
            size_t kb_ = (((size_t)(b * SS + kt * 64 + r)) * 3 + 1) * DD + h * HD + c0;
            const float* ksrc = g_qkv + kb_;
            const float* vsrc = g_qkv + kb_ + DD;
            u32* kd = Ks + r * KST + c0;
            u32* vd = Vs + r * VST + c0;
            #pragma unroll
            for (int j = 0; j < 8; j++) {
                float4 v = *(const float4*)(ksrc + j * 4);
                kd[j*4+0] = to_tf32(v.x); kd[j*4+1] = to_tf32(v.y);
                kd[j*4+2] = to_tf32(v.z); kd[j*4+3] = to_tf32(v.w);
                float4 w = *(const float4*)(vsrc + j * 4);
                vd[j*4+0] = to_tf32(w.x); vd[j*4+1] = to_tf32(w.y);
                vd[j*4+2] = to_tf32(w.z); vd[j*4+3] = to_tf32(w.w);
            }
        }
        __syncthreads();

        float sacc[8][4];
        #pragma unroll
        for (int nt = 0; nt < 8; nt++)
            #pragma unroll
            for (int r = 0; r < 4; r++) sacc[nt][r] = 0.f;

        #pragma unroll
        for (int ks = 0; ks < 8; ks++) {
            int kb = ks * 8;
            #pragma unroll
            for (int nt = 0; nt < 8; nt++) {
                u32 b0 = Ks[(nt * 8 + gid) * KST + kb + tig];
                u32 b1 = Ks[(nt * 8 + gid) * KST + kb + tig + 4];
                asm volatile(
                    "mma.sync.aligned.m16n8k8.row.col.f32.tf32.tf32.f32 "
                    "{%0,%1,%2,%3},{%4,%5,%6,%7},{%8,%9},{%0,%1,%2,%3};"
                    : "+f"(sacc[nt][0]), "+f"(sacc[nt][1]),
                      "+f"(sacc[nt][2]), "+f"(sacc[nt][3])
                    : "r"(qa[ks][0]), "r"(qa[ks][1]),
                      "r"(qa[ks][2]), "r"(qa[ks][3]),
                      "r"(b0), "r"(b1));
            }
        }

        float mt0 = -1e30f, mt1 = -1e30f;
        #pragma unroll
        for (int nt = 0; nt < 8; nt++) {
            sacc[nt][0] *= 0.125f; sacc[nt][1] *= 0.125f;
            sacc[nt][2] *= 0.125f; sacc[nt][3] *= 0.125f;
            mt0 = fmaxf(mt0, fmaxf(sacc[nt][0], sacc[nt][1]));
            mt1 = fmaxf(mt1, fmaxf(sacc[nt][2], sacc[nt][3]));
        }
        mt0 = fmaxf(mt0, __shfl_xor_sync(0xffffffffu, mt0, 1));
        mt0 = fmaxf(mt0, __shfl_xor_sync(0xffffffffu, mt0, 2));
        mt1 = fmaxf(mt1, __shfl_xor_sync(0xffffffffu, mt1, 1));
        mt1 = fmaxf(mt1, __shfl_xor_sync(0xffffffffu, mt1, 2));
        float mn0 = fmaxf(mx0, mt0), mn1 = fmaxf(mx1, mt1);
        float a0 = __expf(mx0 - mn0), a1 = __expf(mx1 - mn1);
        float lt0 = 0.f, lt1 = 0.f;
        #pragma unroll
        for (int nt = 0; nt < 8; nt++) {
            float p0 = __expf(sacc[nt][0] - mn0);
            float p1 = __expf(sacc[nt][1] - mn0);
            float p2 = __expf(sacc[nt][2] - mn1);
            float p3 = __expf(sacc[nt][3] - mn1);
            lt0 += p0 + p1;  lt1 += p2 + p3;
            *(uint2*)&Ps[(m0w + gid)     * KST + nt * 8 + 2 * tig] =
                make_uint2(to_tf32(p0), to_tf32(p1));
            *(uint2*)&Ps[(m0w + gid + 8) * KST + nt * 8 + 2 * tig] =
                make_uint2(to_tf32(p2), to_tf32(p3));
        }
        lt0 += __shfl_xor_sync(0xffffffffu, lt0, 1);
        lt0 += __shfl_xor_sync(0xffffffffu, lt0, 2);
        lt1 += __shfl_xor_sync(0xffffffffu, lt1, 1);
        lt1 += __shfl_xor_sync(0xffffffffu, lt1, 2);
        l0 = l0 * a0 + lt0;  mx0 = mn0;
        l1 = l1 * a1 + lt1;  mx1 = mn1;
        #pragma unroll
        for (int nt = 0; nt < 8; nt++) {
            oa[nt][0] *= a0; oa[nt][1] *= a0;
            oa[nt][2] *= a1; oa[nt][3] *= a1;
        }
        __syncwarp();

        #pragma unroll
        for (int ks = 0; ks < 8; ks++) {
            int kb = ks * 8;
            u32 pa0 = Ps[(m0w + gid)     * KST + kb + tig];
            u32 pa1 = Ps[(m0w + gid + 8) * KST + kb + tig];
            u32 pa2 = Ps[(m0w + gid)     * KST + kb + tig + 4];
            u32 pa3 = Ps[(m0w + gid + 8) * KST + kb + tig + 4];
            #pragma unroll
            for (int nt = 0; nt < 8; nt++) {
                u32 b0 = Vs[(kb + tig)     * VST + nt * 8 + gid];
                u32 b1 = Vs[(kb + tig + 4) * VST + nt * 8 + gid];
                asm volatile(
                    "mma.sync.aligned.m16n8k8.row.col.f32.tf32.tf32.f32 "
                    "{%0,%1,%2,%3},{%4,%5,%6,%7},{%8,%9},{%0,%1,%2,%3};"
                    : "+f"(oa[nt][0]), "+f"(oa[nt][1]),
                      "+f"(oa[nt][2]), "+f"(oa[nt][3])
                    : "r"(pa0), "r"(pa1), "r"(pa2), "r"(pa3),
                      "r"(b0), "r"(b1));
            }
        }
    }

    // epilogue: pre-round to tf32 (g_o feeds the out-proj GEMM only)
    float i0 = 1.f / l0, i1 = 1.f / l1;
    int row0 = qt * 64 + m0w + gid;
    size_t ob0 = ((size_t)(b * SS + row0)) * DD + h * HD;
    size_t ob1 = ob0 + (size_t)8 * DD;
    #pragma unroll
    for (int nt = 0; nt < 8; nt++) {
        int cc = nt * 8 + 2 * tig;
        *(float2*)&g_o[ob0 + cc] = make_float2(to_tf32f(oa[nt][0] * i0),
                                               to_tf32f(oa[nt][1] * i0));
        *(float2*)&g_o[ob1 + cc] = make_float2(to_tf32f(oa[nt][2] * i1),
                                               to_tf32f(oa[nt][3] * i1));
    }
}

// ---------------------------------------------------------------------------
extern "C" void kernel_launch(void* const* d_in, const int* in_sizes, int n_in,
                              void* d_out, int out_size)
{
    const float* x          = (const float*)d_in[0];
    const float* rotary_cos = (const float*)d_in[1];
    const float* rotary_sin = (const float*)d_in[2];
    const float* c          = (const float*)d_in[3];
    const float* norm1_w    = (const float*)d_in[4];
    const float* qkv_w      = (const float*)d_in[5];
    const float* out_w      = (const float*)d_in[6];
    const float* norm2_w    = (const float*)d_in[7];
    const float* fc1_w      = (const float*)d_in[8];
    const float* fc1_b      = (const float*)d_in[9];
    const float* fc2_w      = (const float*)d_in[10];
    const float* fc2_b      = (const float*)d_in[11];
    const float* ada_w      = (const float*)d_in[12];
    const float* ada_b      = (const float*)d_in[13];
    float* out = (float*)d_out;

    float* p_h;    cudaGetSymbolAddress((void**)&p_h, g_h);
    float* p_qkv;  cudaGetSymbolAddress((void**)&p_qkv, g_qkv);
    float* p_o;    cudaGetSymbolAddress((void**)&p_o, g_o);
    float* p_xmid; cudaGetSymbolAddress((void**)&p_xmid, g_xmid);
    float* p_mlp;  cudaGetSymbolAddress((void**)&p_mlp, g_mlp);
    float* p_wq;   cudaGetSymbolAddress((void**)&p_wq, g_wq);
    float* p_wo;   cudaGetSymbolAddress((void**)&p_wo, g_wo);
    float* p_w1;   cudaGetSymbolAddress((void**)&p_w1, g_w1);
    float* p_w2;   cudaGetSymbolAddress((void**)&p_w2, g_w2);

    static int smem_set = 0;
    if (!smem_set) {
        cudaFuncSetAttribute(k_attn,
            cudaFuncAttributeMaxDynamicSharedMemorySize, ATT_SMEM);
        cudaFuncSetAttribute(k_gemm<0>,
            cudaFuncAttributeMaxDynamicSharedMemorySize, GSMEM);
        cudaFuncSetAttribute(k_gemm<1>,
            cudaFuncAttributeMaxDynamicSharedMemorySize, GSMEM);
        cudaFuncSetAttribute(k_gemm<2>,
            cudaFuncAttributeMaxDynamicSharedMemorySize, GSMEM);
        cudaFuncSetAttribute(k_gemm<3>,
            cudaFuncAttributeMaxDynamicSharedMemorySize, GSMEM);
        smem_set = 1;
    }

    // 0) pre-round weights to tf32
    k_wcvt<<<(D3*DD/4 + 255) / 256, 256>>>(qkv_w, p_wq, D3*DD);
    k_wcvt<<<(DD*DD/4 + 255) / 256, 256>>>(out_w, p_wo, DD*DD);
    k_wcvt<<<(D4*DD/4 + 255) / 256, 256>>>(fc1_w, p_w1, D4*DD);
    k_wcvt<<<(DD*D4/4 + 255) / 256, 256>>>(fc2_w, p_w2, DD*D4);

    // 1) adaLN mods
    k_mods<<<(BB * D6 * 32 + 255) / 256, 256>>>(c, ada_w, ada_b);

    // 2) LN1 + modulate (scale_msa @1024, shift_msa @0) -> g_h (tf32)
    k_ln_mod<<<MM, 256>>>(x, norm1_w, 1 * DD, 0 * DD, p_h);

    // 3) QKV GEMM -> g_qkv
    k_gemm<0><<<dim3(D3 / 128, MM / 128), 256, GSMEM>>>(
        p_h, p_wq, nullptr, nullptr, p_qkv, MM, D3, DD, 0);

    // 4) RoPE in place on q,k,v
    k_rope<<<(BB * SS * 3 * HH * 32) / 256, 256>>>(rotary_cos, rotary_sin);

    // 5) Attention -> g_o (tf32)
    k_attn<<<dim3(SS / 64, HH, BB), 128, ATT_SMEM>>>();

    // 6) out proj + gate_msa (@2048) + residual(x) -> g_xmid
    k_gemm<1><<<dim3(DD / 128, MM / 128), 256, GSMEM>>>(
        p_o, p_wo, nullptr, x, p_xmid, MM, DD, DD, 2 * DD);

    // 7) LN2 + modulate (scale_mlp @4096, shift_mlp @3072) -> g_h (tf32)
    k_ln_mod<<<MM, 256>>>(p_xmid, norm2_w, 4 * DD, 3 * DD, p_h);

    // 8) fc1 + bias + exact GELU -> g_mlp (tf32)
    k_gemm<2><<<dim3(D4 / 128, MM / 128), 256, GSMEM>>>(
        p_h, p_w1, fc1_b, nullptr, p_mlp, MM, D4, DD, 0);

    // 9) fc2 + bias, gate_mlp (@5120), + residual(g_xmid) -> d_out
    k_gemm<3><<<dim3(DD / 128, MM / 128), 256, GSMEM>>>(
        p_mlp, p_w2, fc2_b, p_xmid, out, MM, DD, D4, 5 * DD);
}

// round 16
// speedup vs baseline: 1.2020x; 1.2020x over previous
#include <cuda_runtime.h>
#include <cuda_bf16.h>
#include <math.h>

// Problem constants
#define BB 2
#define SS 2048
#define DD 1024
#define HH 16
#define HD 64
#define CC 1024
#define MM (BB*SS)          // 4096 rows
#define D3 (3*DD)           // 3072
#define D4 (4*DD)           // 4096
#define D6 (6*DD)           // 6144

typedef unsigned long long u64;
typedef unsigned int u32;

__device__ __forceinline__ u32 to_tf32(float f) {
    u32 r; asm("cvt.rna.tf32.f32 %0,%1;" : "=r"(r) : "f"(f)); return r;
}

// Scratch (device globals; no allocation allowed)
__device__ float g_mods[BB*D6];
__device__ float g_h[MM*DD];       // LN1 out, later LN2 out
__device__ float g_qkv[MM*D3];
__device__ float g_o[MM*DD];
__device__ float g_xmid[MM*DD];
__device__ float g_mlp[MM*D4];

// ---------------------------------------------------------------------------
// 1) mods = c @ ada_w.T + ada_b
// ---------------------------------------------------------------------------
__global__ void k_mods(const float* __restrict__ c,
                       const float* __restrict__ ada_w,
                       const float* __restrict__ ada_b)
{
    int gw = (blockIdx.x * blockDim.x + threadIdx.x) >> 5;
    int lane = threadIdx.x & 31;
    if (gw >= BB * D6) return;
    int b = gw / D6, j = gw - b * D6;
    const float* cv = c + (size_t)b * CC;
    const float* wv = ada_w + (size_t)j * CC;
    float s = 0.f;
    #pragma unroll 4
    for (int k = lane; k < CC; k += 32) s += cv[k] * wv[k];
    #pragma unroll
    for (int o = 16; o > 0; o >>= 1) s += __shfl_xor_sync(0xffffffffu, s, o);
    if (lane == 0) g_mods[gw] = s + ada_b[j];
}

// ---------------------------------------------------------------------------
// 2) LayerNorm + adaLN modulate
// ---------------------------------------------------------------------------
__global__ void __launch_bounds__(256) k_ln_mod(const float* __restrict__ x,
                                                const float* __restrict__ w,
                                                int scale_off, int shift_off,
                                                float* __restrict__ out)
{
    int row = blockIdx.x;
    int b = row >> 11;
    const float4* xr = (const float4*)(x + (size_t)row * DD);
    int t = threadIdx.x;
    float4 xv = xr[t];
    float s  = xv.x + xv.y + xv.z + xv.w;
    float ss = xv.x*xv.x + xv.y*xv.y + xv.z*xv.z + xv.w*xv.w;
    #pragma unroll
    for (int o = 16; o > 0; o >>= 1) {
        s  += __shfl_xor_sync(0xffffffffu, s, o);
        ss += __shfl_xor_sync(0xffffffffu, ss, o);
    }
    __shared__ float sm[8], sm2[8];
    int wid = t >> 5, lane = t & 31;
    if (lane == 0) { sm[wid] = s; sm2[wid] = ss; }
    __syncthreads();
    if (t == 0) {
        float a = 0.f, a2 = 0.f;
        #pragma unroll
        for (int i = 0; i < 8; i++) { a += sm[i]; a2 += sm2[i]; }
        sm[0] = a; sm2[0] = a2;
    }
    __syncthreads();
    float mu  = sm[0]  * (1.f / DD);
    float var = sm2[0] * (1.f / DD) - mu * mu;
    float rstd = rsqrtf(var + 1e-5f);
    const float* md = g_mods + (size_t)b * D6;
    int j = t * 4;
    float4 wv = *(const float4*)(w + j);
    float4 sc = *(const float4*)(md + scale_off + j);
    float4 sh = *(const float4*)(md + shift_off + j);
    float4 ov;
    ov.x = (xv.x - mu) * rstd * wv.x * (1.f + sc.x) + sh.x;
    ov.y = (xv.y - mu) * rstd * wv.y * (1.f + sc.y) + sh.y;
    ov.z = (xv.z - mu) * rstd * wv.z * (1.f + sc.z) + sh.z;
    ov.w = (xv.w - mu) * rstd * wv.w * (1.f + sc.w) + sh.w;
    ((float4*)(out + (size_t)row * DD))[t] = ov;
}

// ---------------------------------------------------------------------------
// 3) tf32 tensor-core GEMM: C[M,N] = A[M,K] @ Bw[N,K]^T (+ epilogue)
//    128x128x32 tile, 256 threads (8 warps, 4x2), warp = 32 rows x 64 cols
//    via 2x8 m16n8k8 mma tiles. SMEM stride 36 -> conflict-free frag LDS.
//    R6-proven single-buffer schedule (don't touch).
//    EPI: 0=store, 1=gate*acc+add, 2=gelu(acc+bias), 3=gate*(acc+bias)+add,
//         4=fused RoPE (QKV: pair cols n, n+32 within the warp tile)
// ---------------------------------------------------------------------------
#define SMS 36   // smem row stride (u32)

template<int EPI>
__global__ void __launch_bounds__(256) k_gemm(const float* __restrict__ A,
                                              const float* __restrict__ Bw,
                                              const float* __restrict__ bias,
                                              const float* __restrict__ add,
                                              float* __restrict__ C,
                                              int M, int N, int K, int gate_off,
                                              const float* __restrict__ cosT,
                                              const float* __restrict__ sinT)
{
    __shared__ u32 As[128 * SMS];
    __shared__ u32 Bs[128 * SMS];

    const int tid = threadIdx.x;
    const int wid = tid >> 5, lane = tid & 31;
    const int warp_m = wid >> 1;       // 0..3 (32 rows each)
    const int warp_n = wid & 1;        // 0..1 (64 cols each)
    const int gid = lane >> 2, tig = lane & 3;
    const int bm = blockIdx.y * 128, bn = blockIdx.x * 128;

    const int arow = tid >> 1;
    const int ak = (tid & 1) * 16;
    const float* Ap = A  + (size_t)(bm + arow) * K + ak;
    const float* Bp = Bw + (size_t)(bn + arow) * K + ak;

    float acc[2][8][4];
    #pragma unroll
    for (int mt = 0; mt < 2; mt++)
        #pragma unroll
        for (int nt = 0; nt < 8; nt++)
            #pragma unroll
            for (int r = 0; r < 4; r++) acc[mt][nt][r] = 0.f;

    float4 pa[4], pb[4];
    #pragma unroll
    for (int j = 0; j < 4; j++) {
        pa[j] = *(const float4*)(Ap + j * 4);
        pb[j] = *(const float4*)(Bp + j * 4);
    }

    for (int k0 = 0; k0 < K; k0 += 32) {
        __syncthreads();
        #pragma unroll
        for (int j = 0; j < 4; j++) {
            u32* as = &As[arow * SMS + ak + j * 4];
            as[0] = to_tf32(pa[j].x); as[1] = to_tf32(pa[j].y);
            as[2] = to_tf32(pa[j].z); as[3] = to_tf32(pa[j].w);
            u32* bs = &Bs[arow * SMS + ak + j * 4];
            bs[0] = to_tf32(pb[j].x); bs[1] = to_tf32(pb[j].y);
            bs[2] = to_tf32(pb[j].z); bs[3] = to_tf32(pb[j].w);
        }
        __syncthreads();

        if (k0 + 32 < K) {
            #pragma unroll
            for (int j = 0; j < 4; j++) {
                pa[j] = *(const float4*)(Ap + k0 + 32 + j * 4);
                pb[j] = *(const float4*)(Bp + k0 + 32 + j * 4);
            }
        }

        #pragma unroll
        for (int ks = 0; ks < 4; ks++) {
            const int kb = ks * 8;
            u32 afr[2][4];
            #pragma unroll
            for (int mt = 0; mt < 2; mt++) {
                int m0 = warp_m * 32 + mt * 16;
                afr[mt][0] = As[(m0 + gid)     * SMS + kb + tig];
                afr[mt][1] = As[(m0 + gid + 8) * SMS + kb + tig];
                afr[mt][2] = As[(m0 + gid)     * SMS + kb + tig + 4];
                afr[mt][3] = As[(m0 + gid + 8) * SMS + kb + tig + 4];
            }
            u32 bfr[8][2];
            #pragma unroll
            for (int nt = 0; nt < 8; nt++) {
                int n0 = warp_n * 64 + nt * 8;
                bfr[nt][0] = Bs[(n0 + gid) * SMS + kb + tig];
                bfr[nt][1] = Bs[(n0 + gid) * SMS + kb + tig + 4];
            }
            #pragma unroll
            for (int mt = 0; mt < 2; mt++)
                #pragma unroll
                for (int nt = 0; nt < 8; nt++) {
                    asm volatile(
                        "mma.sync.aligned.m16n8k8.row.col.f32.tf32.tf32.f32 "
                        "{%0,%1,%2,%3},{%4,%5,%6,%7},{%8,%9},{%0,%1,%2,%3};"
                        : "+f"(acc[mt][nt][0]), "+f"(acc[mt][nt][1]),
                          "+f"(acc[mt][nt][2]), "+f"(acc[mt][nt][3])
                        : "r"(afr[mt][0]), "r"(afr[mt][1]),
                          "r"(afr[mt][2]), "r"(afr[mt][3]),
                          "r"(bfr[nt][0]), "r"(bfr[nt][1]));
                }
        }
    }

    #pragma unroll
    for (int mt = 0; mt < 2; mt++) {
        #pragma unroll
        for (int half = 0; half < 2; half++) {
            int m = bm + warp_m * 32 + mt * 16 + gid + half * 8;
            int bb = m >> 11;
            if (EPI == 4) {
                // fused RoPE: pair (nt, nt+4) = cols (n, n+32); d = n & 63 < 32
                int s = m & 2047;
                #pragma unroll
                for (int nt = 0; nt < 4; nt++) {
                    int n = bn + warp_n * 64 + nt * 8 + tig * 2;
                    int d = n & 63;
                    float c0  = cosT[s * HD + d],     c1  = cosT[s * HD + d + 1];
                    float sn0 = sinT[s * HD + d],     sn1 = sinT[s * HD + d + 1];
                    float v1a = acc[mt][nt][half*2],     v1b = acc[mt][nt][half*2+1];
                    float v2a = acc[mt][nt+4][half*2],   v2b = acc[mt][nt+4][half*2+1];
                    *(float2*)&C[(size_t)m * N + n] =
                        make_float2(v1a * c0 - v2a * sn0, v1b * c1 - v2b * sn1);
                    *(float2*)&C[(size_t)m * N + n + 32] =
                        make_float2(v2a * c0 + v1a * sn0, v2b * c1 + v1b * sn1);
                }
            } else {
                #pragma unroll
                for (int nt = 0; nt < 8; nt++) {
                    int n = bn + warp_n * 64 + nt * 8 + tig * 2;
                    float v0 = acc[mt][nt][half * 2];
                    float v1 = acc[mt][nt][half * 2 + 1];
                    if (EPI == 0) {
                    } else if (EPI == 1) {
                        v0 = g_mods[(size_t)bb * D6 + gate_off + n]     * v0
                             + add[(size_t)m * N + n];
                        v1 = g_mods[(size_t)bb * D6 + gate_off + n + 1] * v1
                             + add[(size_t)m * N + n + 1];
                    } else if (EPI == 2) {
                        float t0 = v0 + bias[n],     t1 = v1 + bias[n + 1];
                        v0 = 0.5f * t0 * (1.f + erff(t0 * 0.70710678118654752f));
                        v1 = 0.5f * t1 * (1.f + erff(t1 * 0.70710678118654752f));
                    } else {
                        float t0 = v0 + bias[n],     t1 = v1 + bias[n + 1];
                        v0 = g_mods[(size_t)bb * D6 + gate_off + n]     * t0
                             + add[(size_t)m * DD + n];
                        v1 = g_mods[(size_t)bb * D6 + gate_off + n + 1] * t1
                             + add[(size_t)m * DD + n + 1];
                    }
                    *(float2*)&C[(size_t)m * N + n] = make_float2(v0, v1);
                }
            }
        }
    }
}

// ---------------------------------------------------------------------------
// 5) Flash attention on tf32 tensor cores. Br=128, Bc=64, 8 warps (256 thr).
//    Warp w owns query rows [w*16, w*16+16); K/V tiles shared by all 8 warps.
// ---------------------------------------------------------------------------
#define KST 68
#define VST 72
#define ATT_SMEM ((64*KST + 64*VST + 128*KST) * 4)

__global__ void __launch_bounds__(256) k_attn()
{
    extern __shared__ u32 dyn[];
    u32* Ks = dyn;                        // [64][KST]
    u32* Vs = dyn + 64 * KST;             // [64][VST]
    u32* Ps = dyn + 64 * KST + 64 * VST;  // [128][KST] (stages Q then P)

    int qt = blockIdx.x, h = blockIdx.y, b = blockIdx.z;
    int tid = threadIdx.x;
    int wid = tid >> 5, lane = tid & 31;
    int gid = lane >> 2, tig = lane & 3;
    int m0w = wid * 16;

    // Stage Q tile (128x64) into Ps as tf32
    size_t qbase = (((size_t)(b * SS + qt * 128)) * 3 + 0) * DD + h * HD;
    {
        int r = tid >> 1, c0 = (tid & 1) * 32;
        const float* src = g_qkv + qbase + (size_t)r * D3 + c0;
        u32* dst = Ps + r * KST + c0;
        #pragma unroll
        for (int j = 0; j < 8; j++) {
            float4 v = *(const float4*)(src + j * 4);
            dst[j*4+0] = to_tf32(v.x); dst[j*4+1] = to_tf32(v.y);
            dst[j*4+2] = to_tf32(v.z); dst[j*4+3] = to_tf32(v.w);
        }
    }
    __syncthreads();

    u32 qa[8][4];
    #pragma unroll
    for (int ks = 0; ks < 8; ks++) {
        int kb = ks * 8;
        qa[ks][0] = Ps[(m0w + gid)     * KST + kb + tig];
        qa[ks][1] = Ps[(m0w + gid + 8) * KST + kb + tig];
        qa[ks][2] = Ps[(m0w + gid)     * KST + kb + tig + 4];
        qa[ks][3] = Ps[(m0w + gid + 8) * KST + kb + tig + 4];
    }

    float mx0 = -1e30f, mx1 = -1e30f, l0 = 0.f, l1 = 0.f;
    float oa[8][4];
    #pragma unroll
    for (int nt = 0; nt < 8; nt++)
        #pragma unroll
        for (int r = 0; r < 4; r++) oa[nt][r] = 0.f;

    for (int kt = 0; kt < SS / 64; kt++) {
        __syncthreads();   // prior readers of Ks/Vs/Ps done
        {
            int r = tid >> 2, c0 = (tid & 3) * 16;
            size_t kb_ = (((size_t)(b * SS + kt * 64 + r)) * 3 + 1) * DD + h * HD + c0;
            const float* ksrc = g_qkv + kb_;
            const float* vsrc = g_qkv + kb_ + DD;
            u32* kd = Ks + r * KST + c0;
            u32* vd = Vs + r * VST + c0;
            #pragma unroll
            for (int j = 0; j < 4; j++) {
                float4 v = *(const float4*)(ksrc + j * 4);
                kd[j*4+0] = to_tf32(v.x); kd[j*4+1] = to_tf32(v.y);
                kd[j*4+2] = to_tf32(v.z); kd[j*4+3] = to_tf32(v.w);
                float4 w = *(const float4*)(vsrc + j * 4);
                vd[j*4+0] = to_tf32(w.x); vd[j*4+1] = to_tf32(w.y);
                vd[j*4+2] = to_tf32(w.z); vd[j*4+3] = to_tf32(w.w);
            }
        }
        __syncthreads();

        float sacc[8][4];
        #pragma unroll
        for (int nt = 0; nt < 8; nt++)
            #pragma unroll
            for (int r = 0; r < 4; r++) sacc[nt][r] = 0.f;

        #pragma unroll
        for (int ks = 0; ks < 8; ks++) {
            int kb = ks * 8;
            #pragma unroll
            for (int nt = 0; nt < 8; nt++) {
                u32 b0 = Ks[(nt * 8 + gid) * KST + kb + tig];
                u32 b1 = Ks[(nt * 8 + gid) * KST + kb + tig + 4];
                asm volatile(
                    "mma.sync.aligned.m16n8k8.row.col.f32.tf32.tf32.f32 "
                    "{%0,%1,%2,%3},{%4,%5,%6,%7},{%8,%9},{%0,%1,%2,%3};"
                    : "+f"(sacc[nt][0]), "+f"(sacc[nt][1]),
                      "+f"(sacc[nt][2]), "+f"(sacc[nt][3])
                    : "r"(qa[ks][0]), "r"(qa[ks][1]),
                      "r"(qa[ks][2]), "r"(qa[ks][3]),
                      "r"(b0), "r"(b1));
            }
        }

        float mt0 = -1e30f, mt1 = -1e30f;
        #pragma unroll
        for (int nt = 0; nt < 8; nt++) {
            sacc[nt][0] *= 0.125f; sacc[nt][1] *= 0.125f;
            sacc[nt][2] *= 0.125f; sacc[nt][3] *= 0.125f;
            mt0 = fmaxf(mt0, fmaxf(sacc[nt][0], sacc[nt][1]));
            mt1 = fmaxf(mt1, fmaxf(sacc[nt][2], sacc[nt][3]));
        }
        mt0 = fmaxf(mt0, __shfl_xor_sync(0xffffffffu, mt0, 1));
        mt0 = fmaxf(mt0, __shfl_xor_sync(0xffffffffu, mt0, 2));
        mt1 = fmaxf(mt1, __shfl_xor_sync(0xffffffffu, mt1, 1));
        mt1 = fmaxf(mt1, __shfl_xor_sync(0xffffffffu, mt1, 2));
        float mn0 = fmaxf(mx0, mt0), mn1 = fmaxf(mx1, mt1);
        float a0 = __expf(mx0 - mn0), a1 = __expf(mx1 - mn1);
        float lt0 = 0.f, lt1 = 0.f;
        #pragma unroll
        for (int nt = 0; nt < 8; nt++) {
            float p0 = __expf(sacc[nt][0] - mn0);
            float p1 = __expf(sacc[nt][1] - mn0);
            float p2 = __expf(sacc[nt][2] - mn1);
            float p3 = __expf(sacc[nt][3] - mn1);
            lt0 += p0 + p1;  lt1 += p2 + p3;
            *(uint2*)&Ps[(m0w + gid)     * KST + nt * 8 + 2 * tig] =
                make_uint2(to_tf32(p0), to_tf32(p1));
            *(uint2*)&Ps[(m0w + gid + 8) * KST + nt * 8 + 2 * tig] =
                make_uint2(to_tf32(p2), to_tf32(p3));
        }
        lt0 += __shfl_xor_sync(0xffffffffu, lt0, 1);
        lt0 += __shfl_xor_sync(0xffffffffu, lt0, 2);
        lt1 += __shfl_xor_sync(0xffffffffu, lt1, 1);
        lt1 += __shfl_xor_sync(0xffffffffu, lt1, 2);
        l0 = l0 * a0 + lt0;  mx0 = mn0;
        l1 = l1 * a1 + lt1;  mx1 = mn1;
        #pragma unroll
        for (int nt = 0; nt < 8; nt++) {
            oa[nt][0] *= a0; oa[nt][1] *= a0;
            oa[nt][2] *= a1; oa[nt][3] *= a1;
        }
        __syncwarp();   // P rows of this warp written by this warp's lanes

        #pragma unroll
        for (int ks = 0; ks < 8; ks++) {
            int kb = ks * 8;
            u32 pa0 = Ps[(m0w + gid)     * KST + kb + tig];
            u32 pa1 = Ps[(m0w + gid + 8) * KST + kb + tig];
            u32 pa2 = Ps[(m0w + gid)     * KST + kb + tig + 4];
            u32 pa3 = Ps[(m0w + gid + 8) * KST + kb + tig + 4];
            #pragma unroll
            for (int nt = 0; nt < 8; nt++) {
                u32 b0 = Vs[(kb + tig)     * VST + nt * 8 + gid];
                u32 b1 = Vs[(kb + tig + 4) * VST + nt * 8 + gid];
                asm volatile(
                    "mma.sync.aligned.m16n8k8.row.col.f32.tf32.tf32.f32 "
                    "{%0,%1,%2,%3},{%4,%5,%6,%7},{%8,%9},{%0,%1,%2,%3};"
                    : "+f"(oa[nt][0]), "+f"(oa[nt][1]),
                      "+f"(oa[nt][2]), "+f"(oa[nt][3])
                    : "r"(pa0), "r"(pa1), "r"(pa2), "r"(pa3),
                      "r"(b0), "r"(b1));
            }
        }
    }

    float i0 = 1.f / l0, i1 = 1.f / l1;
    int row0 = qt * 128 + m0w + gid;
    size_t ob0 = ((size_t)(b * SS + row0)) * DD + h * HD;
    size_t ob1 = ob0 + (size_t)8 * DD;
    #pragma unroll
    for (int nt = 0; nt < 8; nt++) {
        int cc = nt * 8 + 2 * tig;
        *(float2*)&g_o[ob0 + cc] = make_float2(oa[nt][0] * i0, oa[nt][1] * i0);
        *(float2*)&g_o[ob1 + cc] = make_float2(oa[nt][2] * i1, oa[nt][3] * i1);
    }
}

// ---------------------------------------------------------------------------
extern "C" void kernel_launch(void* const* d_in, const int* in_sizes, int n_in,
                              void* d_out, int out_size)
{
    const float* x          = (const float*)d_in[0];
    const float* rotary_cos = (const float*)d_in[1];
    const float* rotary_sin = (const float*)d_in[2];
    const float* c          = (const float*)d_in[3];
    const float* norm1_w    = (const float*)d_in[4];
    const float* qkv_w      = (const float*)d_in[5];
    const float* out_w      = (const float*)d_in[6];
    const float* norm2_w    = (const float*)d_in[7];
    const float* fc1_w      = (const float*)d_in[8];
    const float* fc1_b      = (const float*)d_in[9];
    const float* fc2_w      = (const float*)d_in[10];
    const float* fc2_b      = (const float*)d_in[11];
    const float* ada_w      = (const float*)d_in[12];
    const float* ada_b      = (const float*)d_in[13];
    float* out = (float*)d_out;

    float* p_h;    cudaGetSymbolAddress((void**)&p_h, g_h);
    float* p_qkv;  cudaGetSymbolAddress((void**)&p_qkv, g_qkv);
    float* p_o;    cudaGetSymbolAddress((void**)&p_o, g_o);
    float* p_xmid; cudaGetSymbolAddress((void**)&p_xmid, g_xmid);
    float* p_mlp;  cudaGetSymbolAddress((void**)&p_mlp, g_mlp);

    static int smem_set = 0;
    if (!smem_set) {
        cudaFuncSetAttribute(k_attn,
            cudaFuncAttributeMaxDynamicSharedMemorySize, ATT_SMEM);
        smem_set = 1;
    }

    // 1) adaLN mods
    k_mods<<<(BB * D6 * 32 + 255) / 256, 256>>>(c, ada_w, ada_b);

    // 2) LN1 + modulate (scale_msa @1024, shift_msa @0) -> g_h
    k_ln_mod<<<MM, 256>>>(x, norm1_w, 1 * DD, 0 * DD, p_h);

    // 3) QKV GEMM with fused RoPE -> g_qkv
    k_gemm<4><<<dim3(D3 / 128, MM / 128), 256>>>(
        p_h, qkv_w, nullptr, nullptr, p_qkv, MM, D3, DD, 0,
        rotary_cos, rotary_sin);

    // 4) Attention -> g_o
    k_attn<<<dim3(SS / 128, HH, BB), 256, ATT_SMEM>>>();

    // 5) out proj + gate_msa (@2048) + residual(x) -> g_xmid
    k_gemm<1><<<dim3(DD / 128, MM / 128), 256>>>(
        p_o, out_w, nullptr, x, p_xmid, MM, DD, DD, 2 * DD,
        nullptr, nullptr);

    // 6) LN2 + modulate (scale_mlp @4096, shift_mlp @3072) -> g_h
    k_ln_mod<<<MM, 256>>>(p_xmid, norm2_w, 4 * DD, 3 * DD, p_h);

    // 7) fc1 + bias + exact GELU -> g_mlp
    k_gemm<2><<<dim3(D4 / 128, MM / 128), 256>>>(
        p_h, fc1_w, fc1_b, nullptr, p_mlp, MM, D4, DD, 0,
        nullptr, nullptr);

    // 8) fc2 + bias, gate_mlp (@5120), + residual(g_xmid) -> d_out
    k_gemm<3><<<dim3(DD / 128, MM / 128), 256>>>(
        p_mlp, fc2_w, fc2_b, p_xmid, out, MM, DD, D4, 5 * DD,
        nullptr, nullptr);
}